// round 2
// baseline (speedup 1.0000x reference)
#include <cuda_runtime.h>
#include <math.h>
#include <stdint.h>

#define BATCH 4
#define SEQ   1024
#define DM    768
#define NH    12
#define HD    64
#define FF    3072
#define NL    6
#define MTOT  (BATCH*SEQ)        // 4096
#define QKVD  (3*DM)             // 2304

// ---------------- scratch (no cudaMalloc allowed) ----------------
__device__ float g_h  [MTOT*DM];    // running hidden state
__device__ float g_qkv[MTOT*QKVD];  // qkv projections
__device__ float g_ctx[MTOT*DM];    // attention context / ffn out
__device__ float g_mid[MTOT*FF];    // ffn intermediate / proj out

// ---------------- positional encoding add ----------------
__global__ void pos_add_kernel(const float* __restrict__ x, float* __restrict__ out) {
    int row = blockIdx.x;            // b*SEQ + s
    int s = row & (SEQ - 1);
    const float c = -logf(10000.0f) / (float)DM;
    for (int d = threadIdx.x; d < DM; d += blockDim.x) {
        int i2 = d & ~1;             // 2*i
        float ang = (float)s * expf((float)i2 * c);
        float pe = (d & 1) ? cosf(ang) : sinf(ang);
        out[(size_t)row*DM + d] = x[(size_t)row*DM + d] + pe;
    }
}

// ---------------- fp32 SGEMM: C[M,N] = A[M,K] @ B[K,N] + bias, optional relu ----
// BM=BN=128, BK=8, 256 threads, 8x8 microtile
__global__ __launch_bounds__(256)
void sgemm_kernel(const float* __restrict__ A, const float* __restrict__ B,
                  const float* __restrict__ bias, float* __restrict__ C,
                  int M, int N, int K, int relu)
{
    __shared__ float As[8][132];
    __shared__ float Bs[8][132];
    const int tid = threadIdx.x;
    const int tx = tid & 15;         // col group (8 cols)
    const int ty = tid >> 4;         // row group (8 rows)
    const int aRow = tid >> 1, aCol = (tid & 1) << 2;
    const int bRow = tid >> 5, bCol = (tid & 31) << 2;
    const float* Ap = A + (size_t)(blockIdx.y*128 + aRow)*K + aCol;
    const float* Bp = B + (size_t)bRow*N + blockIdx.x*128 + bCol;

    float acc[8][8];
#pragma unroll
    for (int i = 0; i < 8; i++)
#pragma unroll
        for (int j = 0; j < 8; j++) acc[i][j] = 0.f;

    for (int k0 = 0; k0 < K; k0 += 8) {
        float4 av = *(const float4*)(Ap + k0);
        float4 bv = *(const float4*)(Bp + (size_t)k0*N);
        As[aCol+0][aRow] = av.x; As[aCol+1][aRow] = av.y;
        As[aCol+2][aRow] = av.z; As[aCol+3][aRow] = av.w;
        *(float4*)&Bs[bRow][bCol] = bv;
        __syncthreads();
#pragma unroll
        for (int kk = 0; kk < 8; kk++) {
            float ar[8], br[8];
#pragma unroll
            for (int i = 0; i < 8; i++) ar[i] = As[kk][ty*8 + i];
#pragma unroll
            for (int j = 0; j < 8; j++) br[j] = Bs[kk][tx*8 + j];
#pragma unroll
            for (int i = 0; i < 8; i++)
#pragma unroll
                for (int j = 0; j < 8; j++) acc[i][j] += ar[i] * br[j];
        }
        __syncthreads();
    }

#pragma unroll
    for (int i = 0; i < 8; i++) {
        int row = blockIdx.y*128 + ty*8 + i;
#pragma unroll
        for (int j = 0; j < 8; j++) {
            int col = blockIdx.x*128 + tx*8 + j;
            float v = acc[i][j] + bias[col];
            if (relu) v = fmaxf(v, 0.f);
            C[(size_t)row*N + col] = v;
        }
    }
}

// ---------------- attention: exact softmax + clip, scores resident in smem ----
// block = (q_tile of 32, head, batch); 256 threads
// smem: Qs[32][64] | Ks[128][65] (also V as [128][64]) | P[32][1024]
#define ATT_SMEM ((32*64 + 128*65 + 32*1024) * sizeof(float))
__global__ __launch_bounds__(256)
void attn_kernel(const float* __restrict__ qkv, float* __restrict__ ctx)
{
    extern __shared__ float sm[];
    float* Qs = sm;                    // 2048
    float* Ks = sm + 32*64;            // 8320 (padded ld=65 for K, ld=64 for V)
    float* P  = sm + 32*64 + 128*65;   // 32768

    const int tid = threadIdx.x;
    const int q0  = blockIdx.x * 32;
    const int h   = blockIdx.y;
    const int b   = blockIdx.z;
    const size_t baseQ = (size_t)b*SEQ*QKVD + h*HD;
    const size_t baseK = baseQ + DM;
    const size_t baseV = baseQ + 2*DM;

    // load Q tile 32x64
    for (int f = tid; f < 32*16; f += 256) {
        int r = f >> 4, c4 = (f & 15) << 2;
        *(float4*)(Qs + r*64 + c4) =
            *(const float4*)(qkv + baseQ + (size_t)(q0 + r)*QKVD + c4);
    }

    // ---- scores: P[32][1024] = scale * Q @ K^T ----
    const float scale = 0.125f;        // 1/sqrt(64)
    const int txs = tid & 31;          // k cols: txs + 32*j
    const int tys = tid >> 5;          // q rows: tys*4 + i
    for (int kt = 0; kt < 8; kt++) {
        for (int f = tid; f < 128*16; f += 256) {
            int r = f >> 4, c4 = (f & 15) << 2;
            float4 v = *(const float4*)(qkv + baseK + (size_t)(kt*128 + r)*QKVD + c4);
            Ks[r*65 + c4+0] = v.x; Ks[r*65 + c4+1] = v.y;
            Ks[r*65 + c4+2] = v.z; Ks[r*65 + c4+3] = v.w;
        }
        __syncthreads();
        float acc[4][4] = {};
#pragma unroll 4
        for (int d = 0; d < 64; d++) {
            float ar[4], br[4];
#pragma unroll
            for (int i = 0; i < 4; i++) ar[i] = Qs[(tys*4 + i)*64 + d];
#pragma unroll
            for (int j = 0; j < 4; j++) br[j] = Ks[(txs + 32*j)*65 + d];
#pragma unroll
            for (int i = 0; i < 4; i++)
#pragma unroll
                for (int j = 0; j < 4; j++) acc[i][j] += ar[i]*br[j];
        }
#pragma unroll
        for (int i = 0; i < 4; i++)
#pragma unroll
            for (int j = 0; j < 4; j++)
                P[(tys*4 + i)*1024 + kt*128 + txs + 32*j] = acc[i][j]*scale;
        __syncthreads();
    }

    // ---- softmax + clip per row (warp per row) ----
    const int warp = tid >> 5, lane = tid & 31;
    for (int r = warp; r < 32; r += 8) {
        float* row = P + r*1024;
        float m = -INFINITY;
        for (int t = lane; t < 1024; t += 32) m = fmaxf(m, row[t]);
#pragma unroll
        for (int o = 16; o; o >>= 1) m = fmaxf(m, __shfl_xor_sync(~0u, m, o));
        float s = 0.f;
        for (int t = lane; t < 1024; t += 32) { float e = expf(row[t] - m); row[t] = e; s += e; }
#pragma unroll
        for (int o = 16; o; o >>= 1) s += __shfl_xor_sync(~0u, s, o);
        float inv = 1.f / s;
        for (int t = lane; t < 1024; t += 32)
            row[t] = fminf(fmaxf(row[t]*inv, 1e-6f), 1.f);
    }
    __syncthreads();

    // ---- O = P @ V  (32x64, K=1024) ----
    const int txo = tid & 15;          // cols: txo + 16*j
    const int tyo = tid >> 4;          // rows: tyo*2 + i
    float o[2][4] = {};
    for (int vt = 0; vt < 8; vt++) {
        for (int f = tid; f < 128*16; f += 256) {
            int r = f >> 4, c4 = (f & 15) << 2;
            *(float4*)(Ks + r*64 + c4) =
                *(const float4*)(qkv + baseV + (size_t)(vt*128 + r)*QKVD + c4);
        }
        __syncthreads();
#pragma unroll 4
        for (int k = 0; k < 128; k++) {
            float p0 = P[(tyo*2 + 0)*1024 + vt*128 + k];
            float p1 = P[(tyo*2 + 1)*1024 + vt*128 + k];
#pragma unroll
            for (int j = 0; j < 4; j++) {
                float v = Ks[k*64 + txo + 16*j];
                o[0][j] += p0*v;
                o[1][j] += p1*v;
            }
        }
        __syncthreads();
    }
#pragma unroll
    for (int i = 0; i < 2; i++)
#pragma unroll
        for (int j = 0; j < 4; j++)
            ctx[((size_t)b*SEQ + q0 + tyo*2 + i)*DM + h*HD + txo + 16*j] = o[i][j];
}

// ---------------- LayerNorm(base [+ delta]) with affine ----------------
__global__ __launch_bounds__(256)
void ln_kernel(const float* __restrict__ base, const float* __restrict__ delta,
               const float* __restrict__ g, const float* __restrict__ bta,
               float* __restrict__ out)
{
    __shared__ float rowv[DM];
    __shared__ float red[256];
    int row = blockIdx.x, tid = threadIdx.x;
    float local = 0.f;
    for (int d = tid; d < DM; d += 256) {
        float v = base[(size_t)row*DM + d];
        if (delta) v += delta[(size_t)row*DM + d];
        rowv[d] = v; local += v;
    }
    red[tid] = local; __syncthreads();
#pragma unroll
    for (int o = 128; o; o >>= 1) { if (tid < o) red[tid] += red[tid + o]; __syncthreads(); }
    float mean = red[0] * (1.0f/DM);
    __syncthreads();
    local = 0.f;
    for (int d = tid; d < DM; d += 256) { float dv = rowv[d] - mean; local += dv*dv; }
    red[tid] = local; __syncthreads();
#pragma unroll
    for (int o = 128; o; o >>= 1) { if (tid < o) red[tid] += red[tid + o]; __syncthreads(); }
    float inv = rsqrtf(red[0] * (1.0f/DM) + 1e-5f);
    for (int d = tid; d < DM; d += 256)
        out[(size_t)row*DM + d] = (rowv[d] - mean)*inv*g[d] + bta[d];
}

// ---------------- orchestration ----------------
extern "C" void kernel_launch(void* const* d_in, const int* in_sizes, int n_in,
                              void* d_out, int out_size)
{
    const float* x    = (const float*)d_in[0];
    const float* Wqkv = (const float*)d_in[1];
    const float* bqkv = (const float*)d_in[2];
    const float* Wo   = (const float*)d_in[3];
    const float* bo   = (const float*)d_in[4];
    const float* ln1g = (const float*)d_in[5];
    const float* ln1b = (const float*)d_in[6];
    const float* W1   = (const float*)d_in[7];
    const float* b1   = (const float*)d_in[8];
    const float* W2   = (const float*)d_in[9];
    const float* b2   = (const float*)d_in[10];
    const float* ln2g = (const float*)d_in[11];
    const float* ln2b = (const float*)d_in[12];
    const float* lnfg = (const float*)d_in[13];
    const float* lnfb = (const float*)d_in[14];
    float* out = (float*)d_out;

    float *h, *qkv, *ctx, *mid;
    cudaGetSymbolAddress((void**)&h,   g_h);
    cudaGetSymbolAddress((void**)&qkv, g_qkv);
    cudaGetSymbolAddress((void**)&ctx, g_ctx);
    cudaGetSymbolAddress((void**)&mid, g_mid);

    cudaFuncSetAttribute(attn_kernel, cudaFuncAttributeMaxDynamicSharedMemorySize,
                         (int)ATT_SMEM);

    pos_add_kernel<<<MTOT, 256>>>(x, h);

    for (int l = 0; l < NL; l++) {
        // qkv = h @ Wqkv + bqkv
        sgemm_kernel<<<dim3(QKVD/128, MTOT/128), 256>>>(
            h, Wqkv + (size_t)l*DM*QKVD, bqkv + (size_t)l*QKVD, qkv,
            MTOT, QKVD, DM, 0);
        // attention -> ctx
        attn_kernel<<<dim3(SEQ/32, NH, BATCH), 256, ATT_SMEM>>>(qkv, ctx);
        // proj = ctx @ Wo + bo  (into mid front)
        sgemm_kernel<<<dim3(DM/128, MTOT/128), 256>>>(
            ctx, Wo + (size_t)l*DM*DM, bo + (size_t)l*DM, mid,
            MTOT, DM, DM, 0);
        // h = LN(h + proj)
        ln_kernel<<<MTOT, 256>>>(h, mid, ln1g + (size_t)l*DM, ln1b + (size_t)l*DM, h);
        // mid = relu(h @ W1 + b1)
        sgemm_kernel<<<dim3(FF/128, MTOT/128), 256>>>(
            h, W1 + (size_t)l*DM*FF, b1 + (size_t)l*FF, mid,
            MTOT, FF, DM, 1);
        // ctx = mid @ W2 + b2
        sgemm_kernel<<<dim3(DM/128, MTOT/128), 256>>>(
            mid, W2 + (size_t)l*FF*DM, b2 + (size_t)l*DM, ctx,
            MTOT, DM, FF, 0);
        // h = LN(h + ffn)
        ln_kernel<<<MTOT, 256>>>(h, ctx, ln2g + (size_t)l*DM, ln2b + (size_t)l*DM, h);
    }

    // final LN -> out
    ln_kernel<<<MTOT, 256>>>(h, nullptr, lnfg, lnfb, out);
}

// round 3
// speedup vs baseline: 1.7365x; 1.7365x over previous
#include <cuda_runtime.h>
#include <math.h>
#include <stdint.h>

#define BATCH 4
#define SEQ   1024
#define DM    768
#define NH    12
#define HD    64
#define FF    3072
#define NL    6
#define MTOT  (BATCH*SEQ)        // 4096
#define QKVD  (3*DM)             // 2304

// ---------------- scratch (no cudaMalloc allowed) ----------------
__device__ float g_h  [MTOT*DM];
__device__ float g_qkv[MTOT*QKVD];
__device__ float g_ctx[MTOT*DM];
__device__ float g_mid[MTOT*FF];

typedef unsigned long long u64;

__device__ __forceinline__ u64 ffma2(u64 a, u64 b, u64 c) {
    u64 d;
    asm("fma.rn.f32x2 %0,%1,%2,%3;" : "=l"(d) : "l"(a), "l"(b), "l"(c));
    return d;
}
__device__ __forceinline__ u64 pack_dup(float x) {
    u64 d;
    asm("mov.b64 %0,{%1,%1};" : "=l"(d) : "r"(__float_as_uint(x)));
    return d;
}

// ---------------- positional encoding add ----------------
__global__ void pos_add_kernel(const float* __restrict__ x, float* __restrict__ out) {
    int row = blockIdx.x;
    int s = row & (SEQ - 1);
    const float c = -logf(10000.0f) / (float)DM;
    for (int d = threadIdx.x; d < DM; d += blockDim.x) {
        int i2 = d & ~1;
        float ang = (float)s * expf((float)i2 * c);
        float pe = (d & 1) ? cosf(ang) : sinf(ang);
        out[(size_t)row*DM + d] = x[(size_t)row*DM + d] + pe;
    }
}

// ---------------- fp32 SGEMM, double-buffered, packed f32x2 FMA ----------------
// BM=BN=128, BK=16, 256 threads, 8x8 microtile (as 8x4 f32x2 pairs)
__global__ __launch_bounds__(256, 2)
void sgemm_kernel(const float* __restrict__ A, const float* __restrict__ B,
                  const float* __restrict__ bias, float* __restrict__ C,
                  int M, int N, int K, int relu)
{
    __shared__ float As[2][16][128];   // [k][m]
    __shared__ float Bs[2][16][128];   // [k][n]

    const int tid = threadIdx.x;
    const int tx = tid & 15;           // n group (8 cols)
    const int ty = tid >> 4;           // m group (8 rows)
    const int m0 = blockIdx.y * 128;
    const int n0 = blockIdx.x * 128;

    // global-load mapping: A: f -> m=f>>2, k4=(f&3)*4 ; B: f -> k=f>>5, n4=(f&31)*4
    const int am[2] = { tid >> 2, 64 + (tid >> 2) };
    const int ak    = (tid & 3) << 2;
    const int bk[2] = { tid >> 5, 8 + (tid >> 5) };
    const int bn    = (tid & 31) << 2;

    const float* Abase = A + (size_t)m0 * K + ak;
    const float* Bbase = B + n0 + bn;

    float4 pa[2], pb[2];
    // preload tile 0
#pragma unroll
    for (int i = 0; i < 2; i++) {
        pa[i] = *(const float4*)(Abase + (size_t)am[i]*K);
        pb[i] = *(const float4*)(Bbase + (size_t)bk[i]*N);
    }
    {
        int buf = 0;
#pragma unroll
        for (int i = 0; i < 2; i++) {
            As[buf][ak+0][am[i]] = pa[i].x;
            As[buf][ak+1][am[i]] = pa[i].y;
            As[buf][ak+2][am[i]] = pa[i].z;
            As[buf][ak+3][am[i]] = pa[i].w;
            *(float4*)&Bs[buf][bk[i]][bn] = pb[i];
        }
    }
    __syncthreads();

    u64 acc[8][4];
#pragma unroll
    for (int i = 0; i < 8; i++)
#pragma unroll
        for (int j = 0; j < 4; j++) acc[i][j] = 0ull;

    const int nt = K >> 4;
    int buf = 0;
    for (int t = 0; t < nt; t++) {
        if (t + 1 < nt) {
            int k0 = (t + 1) << 4;
#pragma unroll
            for (int i = 0; i < 2; i++) {
                pa[i] = *(const float4*)(Abase + (size_t)am[i]*K + k0);
                pb[i] = *(const float4*)(Bbase + (size_t)(k0 + bk[i])*N);
            }
        }
#pragma unroll
        for (int kk = 0; kk < 16; kk++) {
            float4 a0 = *(const float4*)&As[buf][kk][ty*8];
            float4 a1 = *(const float4*)&As[buf][kk][ty*8 + 4];
            ulonglong2 b0 = *(const ulonglong2*)&Bs[buf][kk][tx*8];
            ulonglong2 b1 = *(const ulonglong2*)&Bs[buf][kk][tx*8 + 4];
            u64 ad[8];
            ad[0] = pack_dup(a0.x); ad[1] = pack_dup(a0.y);
            ad[2] = pack_dup(a0.z); ad[3] = pack_dup(a0.w);
            ad[4] = pack_dup(a1.x); ad[5] = pack_dup(a1.y);
            ad[6] = pack_dup(a1.z); ad[7] = pack_dup(a1.w);
#pragma unroll
            for (int i = 0; i < 8; i++) {
                acc[i][0] = ffma2(ad[i], b0.x, acc[i][0]);
                acc[i][1] = ffma2(ad[i], b0.y, acc[i][1]);
                acc[i][2] = ffma2(ad[i], b1.x, acc[i][2]);
                acc[i][3] = ffma2(ad[i], b1.y, acc[i][3]);
            }
        }
        if (t + 1 < nt) {
            int nb = buf ^ 1;
#pragma unroll
            for (int i = 0; i < 2; i++) {
                As[nb][ak+0][am[i]] = pa[i].x;
                As[nb][ak+1][am[i]] = pa[i].y;
                As[nb][ak+2][am[i]] = pa[i].z;
                As[nb][ak+3][am[i]] = pa[i].w;
                *(float4*)&Bs[nb][bk[i]][bn] = pb[i];
            }
            __syncthreads();
            buf = nb;
        }
    }

    // epilogue
#pragma unroll
    for (int i = 0; i < 8; i++) {
        int row = m0 + ty*8 + i;
#pragma unroll
        for (int j = 0; j < 4; j++) {
            int col = n0 + tx*8 + j*2;
            float c0 = __uint_as_float((unsigned)(acc[i][j] & 0xffffffffull));
            float c1 = __uint_as_float((unsigned)(acc[i][j] >> 32));
            c0 += bias[col];
            c1 += bias[col + 1];
            if (relu) { c0 = fmaxf(c0, 0.f); c1 = fmaxf(c1, 0.f); }
            float2 v = make_float2(c0, c1);
            *(float2*)&C[(size_t)row*N + col] = v;
        }
    }
}

// ---------------- attention (unchanged from R1) ----------------
#define ATT_SMEM ((32*64 + 128*65 + 32*1024) * sizeof(float))
__global__ __launch_bounds__(256)
void attn_kernel(const float* __restrict__ qkv, float* __restrict__ ctx)
{
    extern __shared__ float sm[];
    float* Qs = sm;
    float* Ks = sm + 32*64;
    float* P  = sm + 32*64 + 128*65;

    const int tid = threadIdx.x;
    const int q0  = blockIdx.x * 32;
    const int h   = blockIdx.y;
    const int b   = blockIdx.z;
    const size_t baseQ = (size_t)b*SEQ*QKVD + h*HD;
    const size_t baseK = baseQ + DM;
    const size_t baseV = baseQ + 2*DM;

    for (int f = tid; f < 32*16; f += 256) {
        int r = f >> 4, c4 = (f & 15) << 2;
        *(float4*)(Qs + r*64 + c4) =
            *(const float4*)(qkv + baseQ + (size_t)(q0 + r)*QKVD + c4);
    }

    const float scale = 0.125f;
    const int txs = tid & 31;
    const int tys = tid >> 5;
    for (int kt = 0; kt < 8; kt++) {
        for (int f = tid; f < 128*16; f += 256) {
            int r = f >> 4, c4 = (f & 15) << 2;
            float4 v = *(const float4*)(qkv + baseK + (size_t)(kt*128 + r)*QKVD + c4);
            Ks[r*65 + c4+0] = v.x; Ks[r*65 + c4+1] = v.y;
            Ks[r*65 + c4+2] = v.z; Ks[r*65 + c4+3] = v.w;
        }
        __syncthreads();
        float acc[4][4] = {};
#pragma unroll 4
        for (int d = 0; d < 64; d++) {
            float ar[4], br[4];
#pragma unroll
            for (int i = 0; i < 4; i++) ar[i] = Qs[(tys*4 + i)*64 + d];
#pragma unroll
            for (int j = 0; j < 4; j++) br[j] = Ks[(txs + 32*j)*65 + d];
#pragma unroll
            for (int i = 0; i < 4; i++)
#pragma unroll
                for (int j = 0; j < 4; j++) acc[i][j] += ar[i]*br[j];
        }
#pragma unroll
        for (int i = 0; i < 4; i++)
#pragma unroll
            for (int j = 0; j < 4; j++)
                P[(tys*4 + i)*1024 + kt*128 + txs + 32*j] = acc[i][j]*scale;
        __syncthreads();
    }

    const int warp = tid >> 5, lane = tid & 31;
    for (int r = warp; r < 32; r += 8) {
        float* row = P + r*1024;
        float m = -INFINITY;
        for (int t = lane; t < 1024; t += 32) m = fmaxf(m, row[t]);
#pragma unroll
        for (int o = 16; o; o >>= 1) m = fmaxf(m, __shfl_xor_sync(~0u, m, o));
        float s = 0.f;
        for (int t = lane; t < 1024; t += 32) { float e = expf(row[t] - m); row[t] = e; s += e; }
#pragma unroll
        for (int o = 16; o; o >>= 1) s += __shfl_xor_sync(~0u, s, o);
        float inv = 1.f / s;
        for (int t = lane; t < 1024; t += 32)
            row[t] = fminf(fmaxf(row[t]*inv, 1e-6f), 1.f);
    }
    __syncthreads();

    const int txo = tid & 15;
    const int tyo = tid >> 4;
    float o[2][4] = {};
    for (int vt = 0; vt < 8; vt++) {
        for (int f = tid; f < 128*16; f += 256) {
            int r = f >> 4, c4 = (f & 15) << 2;
            *(float4*)(Ks + r*64 + c4) =
                *(const float4*)(qkv + baseV + (size_t)(vt*128 + r)*QKVD + c4);
        }
        __syncthreads();
#pragma unroll 4
        for (int k = 0; k < 128; k++) {
            float p0 = P[(tyo*2 + 0)*1024 + vt*128 + k];
            float p1 = P[(tyo*2 + 1)*1024 + vt*128 + k];
#pragma unroll
            for (int j = 0; j < 4; j++) {
                float v = Ks[k*64 + txo + 16*j];
                o[0][j] += p0*v;
                o[1][j] += p1*v;
            }
        }
        __syncthreads();
    }
#pragma unroll
    for (int i = 0; i < 2; i++)
#pragma unroll
        for (int j = 0; j < 4; j++)
            ctx[((size_t)b*SEQ + q0 + tyo*2 + i)*DM + h*HD + txo + 16*j] = o[i][j];
}

// ---------------- LayerNorm ----------------
__global__ __launch_bounds__(256)
void ln_kernel(const float* __restrict__ base, const float* __restrict__ delta,
               const float* __restrict__ g, const float* __restrict__ bta,
               float* __restrict__ out)
{
    __shared__ float rowv[DM];
    __shared__ float red[256];
    int row = blockIdx.x, tid = threadIdx.x;
    float local = 0.f;
    for (int d = tid; d < DM; d += 256) {
        float v = base[(size_t)row*DM + d];
        if (delta) v += delta[(size_t)row*DM + d];
        rowv[d] = v; local += v;
    }
    red[tid] = local; __syncthreads();
#pragma unroll
    for (int o = 128; o; o >>= 1) { if (tid < o) red[tid] += red[tid + o]; __syncthreads(); }
    float mean = red[0] * (1.0f/DM);
    __syncthreads();
    local = 0.f;
    for (int d = tid; d < DM; d += 256) { float dv = rowv[d] - mean; local += dv*dv; }
    red[tid] = local; __syncthreads();
#pragma unroll
    for (int o = 128; o; o >>= 1) { if (tid < o) red[tid] += red[tid + o]; __syncthreads(); }
    float inv = rsqrtf(red[0] * (1.0f/DM) + 1e-5f);
    for (int d = tid; d < DM; d += 256)
        out[(size_t)row*DM + d] = (rowv[d] - mean)*inv*g[d] + bta[d];
}

// ---------------- orchestration ----------------
extern "C" void kernel_launch(void* const* d_in, const int* in_sizes, int n_in,
                              void* d_out, int out_size)
{
    const float* x    = (const float*)d_in[0];
    const float* Wqkv = (const float*)d_in[1];
    const float* bqkv = (const float*)d_in[2];
    const float* Wo   = (const float*)d_in[3];
    const float* bo   = (const float*)d_in[4];
    const float* ln1g = (const float*)d_in[5];
    const float* ln1b = (const float*)d_in[6];
    const float* W1   = (const float*)d_in[7];
    const float* b1   = (const float*)d_in[8];
    const float* W2   = (const float*)d_in[9];
    const float* b2   = (const float*)d_in[10];
    const float* ln2g = (const float*)d_in[11];
    const float* ln2b = (const float*)d_in[12];
    const float* lnfg = (const float*)d_in[13];
    const float* lnfb = (const float*)d_in[14];
    float* out = (float*)d_out;

    float *h, *qkv, *ctx, *mid;
    cudaGetSymbolAddress((void**)&h,   g_h);
    cudaGetSymbolAddress((void**)&qkv, g_qkv);
    cudaGetSymbolAddress((void**)&ctx, g_ctx);
    cudaGetSymbolAddress((void**)&mid, g_mid);

    cudaFuncSetAttribute(attn_kernel, cudaFuncAttributeMaxDynamicSharedMemorySize,
                         (int)ATT_SMEM);

    pos_add_kernel<<<MTOT, 256>>>(x, h);

    for (int l = 0; l < NL; l++) {
        sgemm_kernel<<<dim3(QKVD/128, MTOT/128), 256>>>(
            h, Wqkv + (size_t)l*DM*QKVD, bqkv + (size_t)l*QKVD, qkv,
            MTOT, QKVD, DM, 0);
        attn_kernel<<<dim3(SEQ/32, NH, BATCH), 256, ATT_SMEM>>>(qkv, ctx);
        sgemm_kernel<<<dim3(DM/128, MTOT/128), 256>>>(
            ctx, Wo + (size_t)l*DM*DM, bo + (size_t)l*DM, mid,
            MTOT, DM, DM, 0);
        ln_kernel<<<MTOT, 256>>>(h, mid, ln1g + (size_t)l*DM, ln1b + (size_t)l*DM, h);
        sgemm_kernel<<<dim3(FF/128, MTOT/128), 256>>>(
            h, W1 + (size_t)l*DM*FF, b1 + (size_t)l*FF, mid,
            MTOT, FF, DM, 1);
        sgemm_kernel<<<dim3(DM/128, MTOT/128), 256>>>(
            mid, W2 + (size_t)l*FF*DM, b2 + (size_t)l*DM, ctx,
            MTOT, DM, FF, 0);
        ln_kernel<<<MTOT, 256>>>(h, ctx, ln2g + (size_t)l*DM, ln2b + (size_t)l*DM, h);
    }

    ln_kernel<<<MTOT, 256>>>(h, nullptr, lnfg, lnfb, out);
}